// round 6
// baseline (speedup 1.0000x reference)
#include <cuda_runtime.h>
#include <math.h>
#include <float.h>
#include <stdint.h>

#define BATCH   2
#define SEQ     2048
#define DMODEL  1024
#define NHEADS  16
#define HDIM    64
#define MROWS   (BATCH*SEQ)     // 4096
#define QKVN    (3*DMODEL)      // 3072
#define BHT     (BATCH*NHEADS)  // 32

// ---------------- scratch (device globals; no allocations allowed) ----------
static __device__ float g_qkv[(size_t)MROWS * QKVN];
static __device__ float g_q  [(size_t)BHT * SEQ * HDIM];
static __device__ float g_k  [(size_t)BHT * SEQ * HDIM];
static __device__ float g_v  [(size_t)BHT * SEQ * HDIM];
static __device__ float g_o  [(size_t)BHT * SEQ * HDIM];
static __device__ float g_ao [(size_t)MROWS * DMODEL];

// ---------------- tf32 helpers ----------------
__device__ __forceinline__ uint32_t f2tf(float f) {
    uint32_t u;
    asm("cvt.rna.tf32.f32 %0, %1;" : "=r"(u) : "f"(f));
    return u;
}

// D = A(16x8) * B(8x8) + D, tf32 in / fp32 out
__device__ __forceinline__ void mma8(float* d, const uint32_t* a, uint32_t b0, uint32_t b1) {
    asm volatile(
        "mma.sync.aligned.m16n8k8.row.col.f32.tf32.tf32.f32 "
        "{%0,%1,%2,%3}, {%4,%5,%6,%7}, {%8,%9}, {%0,%1,%2,%3};"
        : "+f"(d[0]), "+f"(d[1]), "+f"(d[2]), "+f"(d[3])
        : "r"(a[0]), "r"(a[1]), "r"(a[2]), "r"(a[3]), "r"(b0), "r"(b1));
}

// ============ TF32 tensor-core GEMM: C[M,N] = A[M,K] * B[N,K]^T + bias[N] ===
// 128x128 block, k16 chunks, 256 threads = 8 warps (2m x 4n), warp tile 64x32.
// smem tiles stored [row][k] with pad GP=20 -> conflict-free frag LDS + STS.128.
#define GP 20
__global__ __launch_bounds__(256)
void gemm_tf32_nt_bias(const float* __restrict__ A, const float* __restrict__ B,
                       const float* __restrict__ bias, float* __restrict__ C,
                       int M, int N, int K)
{
    __shared__ uint32_t As[128 * GP];
    __shared__ uint32_t Bs[128 * GP];

    const int tid  = threadIdx.x;
    const int warp = tid >> 5, lane = tid & 31;
    const int g    = lane >> 2, tig = lane & 3;
    const int wm   = (warp >> 2) * 64;
    const int wn   = (warp & 3) * 32;
    const int bm   = blockIdx.y * 128;
    const int bn   = blockIdx.x * 128;

    // load mapping: 8 lanes = 8 consecutive rows with same kc (STS.128 phases clean)
    const int kc = ((tid >> 3) & 3) << 2;          // 0,4,8,12
    const int r0 = (tid & 7) + ((tid >> 5) << 3);  // 0..63

    float acc[4][4][4];
#pragma unroll
    for (int mt = 0; mt < 4; mt++)
#pragma unroll
        for (int nt = 0; nt < 4; nt++)
#pragma unroll
            for (int j = 0; j < 4; j++) acc[mt][nt][j] = 0.f;

    float4 ra0, ra1, rb0, rb1;
    ra0 = *reinterpret_cast<const float4*>(A + (size_t)(bm + r0)      * K + kc);
    ra1 = *reinterpret_cast<const float4*>(A + (size_t)(bm + r0 + 64) * K + kc);
    rb0 = *reinterpret_cast<const float4*>(B + (size_t)(bn + r0)      * K + kc);
    rb1 = *reinterpret_cast<const float4*>(B + (size_t)(bn + r0 + 64) * K + kc);
    {
        uint4 u;
        u.x = f2tf(ra0.x); u.y = f2tf(ra0.y); u.z = f2tf(ra0.z); u.w = f2tf(ra0.w);
        *reinterpret_cast<uint4*>(&As[r0 * GP + kc]) = u;
        u.x = f2tf(ra1.x); u.y = f2tf(ra1.y); u.z = f2tf(ra1.z); u.w = f2tf(ra1.w);
        *reinterpret_cast<uint4*>(&As[(r0 + 64) * GP + kc]) = u;
        u.x = f2tf(rb0.x); u.y = f2tf(rb0.y); u.z = f2tf(rb0.z); u.w = f2tf(rb0.w);
        *reinterpret_cast<uint4*>(&Bs[r0 * GP + kc]) = u;
        u.x = f2tf(rb1.x); u.y = f2tf(rb1.y); u.z = f2tf(rb1.z); u.w = f2tf(rb1.w);
        *reinterpret_cast<uint4*>(&Bs[(r0 + 64) * GP + kc]) = u;
    }
    __syncthreads();

    for (int kt = 0; kt < K; kt += 16) {
        const bool nxt = (kt + 16) < K;
        if (nxt) {
            ra0 = *reinterpret_cast<const float4*>(A + (size_t)(bm + r0)      * K + kt + 16 + kc);
            ra1 = *reinterpret_cast<const float4*>(A + (size_t)(bm + r0 + 64) * K + kt + 16 + kc);
            rb0 = *reinterpret_cast<const float4*>(B + (size_t)(bn + r0)      * K + kt + 16 + kc);
            rb1 = *reinterpret_cast<const float4*>(B + (size_t)(bn + r0 + 64) * K + kt + 16 + kc);
        }
#pragma unroll
        for (int ks = 0; ks < 16; ks += 8) {
            uint32_t af[4][4];
#pragma unroll
            for (int mt = 0; mt < 4; mt++) {
                int m0 = wm + mt * 16 + g;
                af[mt][0] = As[m0 * GP + ks + tig];
                af[mt][1] = As[(m0 + 8) * GP + ks + tig];
                af[mt][2] = As[m0 * GP + ks + tig + 4];
                af[mt][3] = As[(m0 + 8) * GP + ks + tig + 4];
            }
#pragma unroll
            for (int nt = 0; nt < 4; nt++) {
                int n0 = wn + nt * 8 + g;
                uint32_t b0 = Bs[n0 * GP + ks + tig];
                uint32_t b1 = Bs[n0 * GP + ks + tig + 4];
#pragma unroll
                for (int mt = 0; mt < 4; mt++)
                    mma8(acc[mt][nt], af[mt], b0, b1);
            }
        }
        if (nxt) {
            __syncthreads();
            uint4 u;
            u.x = f2tf(ra0.x); u.y = f2tf(ra0.y); u.z = f2tf(ra0.z); u.w = f2tf(ra0.w);
            *reinterpret_cast<uint4*>(&As[r0 * GP + kc]) = u;
            u.x = f2tf(ra1.x); u.y = f2tf(ra1.y); u.z = f2tf(ra1.z); u.w = f2tf(ra1.w);
            *reinterpret_cast<uint4*>(&As[(r0 + 64) * GP + kc]) = u;
            u.x = f2tf(rb0.x); u.y = f2tf(rb0.y); u.z = f2tf(rb0.z); u.w = f2tf(rb0.w);
            *reinterpret_cast<uint4*>(&Bs[r0 * GP + kc]) = u;
            u.x = f2tf(rb1.x); u.y = f2tf(rb1.y); u.z = f2tf(rb1.z); u.w = f2tf(rb1.w);
            *reinterpret_cast<uint4*>(&Bs[(r0 + 64) * GP + kc]) = u;
            __syncthreads();
        }
    }

#pragma unroll
    for (int nt = 0; nt < 4; nt++) {
        int cc = bn + wn + nt * 8 + 2 * tig;
        float bv0 = bias[cc], bv1 = bias[cc + 1];
#pragma unroll
        for (int mt = 0; mt < 4; mt++) {
            int rr = bm + wm + mt * 16 + g;
            float2 v0, v1;
            v0.x = acc[mt][nt][0] + bv0; v0.y = acc[mt][nt][1] + bv1;
            v1.x = acc[mt][nt][2] + bv0; v1.y = acc[mt][nt][3] + bv1;
            *reinterpret_cast<float2*>(C + (size_t)rr * N + cc)       = v0;
            *reinterpret_cast<float2*>(C + (size_t)(rr + 8) * N + cc) = v1;
        }
    }
}

// ---------------- RoPE + split qkv[M,3*D] -> q/k/v [B,H,S,Hd] ----------------
__global__ void rope_split_kernel(const float* __restrict__ qkv,
                                  float* __restrict__ q, float* __restrict__ k,
                                  float* __restrict__ v)
{
    int idx = blockIdx.x * blockDim.x + threadIdx.x;
    if (idx >= MROWS * NHEADS * (HDIM / 2)) return;
    int j = idx & 31;
    int h = (idx >> 5) & 15;
    int m = idx >> 9;
    int b = m >> 11;
    int s = m & 2047;

    float inv_freq = 1.0f / powf(10000.0f, (float)j * (1.0f / 32.0f));
    float ang = (float)s * inv_freq;
    float sn, c;
    sincosf(ang, &sn, &c);

    size_t ib = (size_t)m * QKVN + (size_t)h * HDIM;
    size_t ob = ((size_t)(b * NHEADS + h) * SEQ + s) * HDIM;

    float q1 = qkv[ib + j],          q2 = qkv[ib + 32 + j];
    q[ob + j]      = q1 * c  - q2 * sn;
    q[ob + 32 + j] = q1 * sn + q2 * c;

    float k1 = qkv[ib + DMODEL + j], k2 = qkv[ib + DMODEL + 32 + j];
    k[ob + j]      = k1 * c  - k2 * sn;
    k[ob + 32 + j] = k1 * sn + k2 * c;

    v[ob + j]      = qkv[ib + 2 * DMODEL + j];
    v[ob + 32 + j] = qkv[ib + 2 * DMODEL + 32 + j];
}

// ============ TF32 tensor-core causal flash attention ============
// BQ=128, BK=64, 256 threads = 8 warps, warp owns 16 q-rows (no cross-warp
// softmax). smem pad AP=68 -> conflict-free fragment LDS.
#define AP 68
#define ATTN_SMEM ((128 + 64 + 64 + 128) * AP * 4)
__global__ __launch_bounds__(256)
void attn_tc_kernel(const float* __restrict__ Q, const float* __restrict__ K,
                    const float* __restrict__ V, float* __restrict__ O)
{
    extern __shared__ uint32_t sm_u[];
    uint32_t* Qs = sm_u;               // [128][AP]  Q rows (tf32)
    uint32_t* Ks = Qs + 128 * AP;      // [64][AP]   K rows (tf32)
    uint32_t* Vt = Ks + 64 * AP;       // [64][AP]   V transposed: [d][kcol]
    uint32_t* Ps = Vt + 64 * AP;       // [128][AP]  P rows (tf32)

    const int tid  = threadIdx.x;
    const int warp = tid >> 5, lane = tid & 31;
    const int g    = lane >> 2, tig = lane & 3;
    const int wm   = warp * 16;
    const int bh   = blockIdx.y;
    const int qi   = gridDim.x - 1 - blockIdx.x;   // heavy blocks first
    const int q0   = qi * 128;

    const float* Qb = Q + (size_t)bh * SEQ * HDIM;
    const float* Kb = K + (size_t)bh * SEQ * HDIM;
    const float* Vb = V + (size_t)bh * SEQ * HDIM;

    // load Q tile (128x64), row-major, tf32
#pragma unroll
    for (int p = 0; p < 8; p++) {
        int idx = tid + p * 256;
        int row = idx >> 4, c4 = (idx & 15) << 2;
        float4 val = *reinterpret_cast<const float4*>(Qb + (size_t)(q0 + row) * HDIM + c4);
        uint4 u;
        u.x = f2tf(val.x); u.y = f2tf(val.y); u.z = f2tf(val.z); u.w = f2tf(val.w);
        *reinterpret_cast<uint4*>(&Qs[row * AP + c4]) = u;
    }

    float oacc[8][4];
#pragma unroll
    for (int nt = 0; nt < 8; nt++)
#pragma unroll
        for (int j = 0; j < 4; j++) oacc[nt][j] = 0.f;
    float m0 = -1e30f, m1 = -1e30f, l0 = 0.f, l1 = 0.f;

    const int vk = tid & 63;           // kcol owned for V transpose store
    const int vd = (tid >> 6) << 2;    // d4 base

    const int rg0 = q0 + wm + g;
    const int rg1 = rg0 + 8;

    const int nkt = (q0 >> 6) + 2;
    for (int kt = 0; kt < nkt; kt++) {
        const int kg = kt << 6;
        __syncthreads();   // previous iteration's consumers of Ks/Vt done
        // K tile [64][64] row-major
#pragma unroll
        for (int p = 0; p < 4; p++) {
            int idx = tid + p * 256;
            int row = idx >> 4, c4 = (idx & 15) << 2;
            float4 kv = *reinterpret_cast<const float4*>(Kb + (size_t)(kg + row) * HDIM + c4);
            uint4 u;
            u.x = f2tf(kv.x); u.y = f2tf(kv.y); u.z = f2tf(kv.z); u.w = f2tf(kv.w);
            *reinterpret_cast<uint4*>(&Ks[row * AP + c4]) = u;
        }
        // V tile transposed to [d][kcol] (lanes = consecutive kcols -> STS conflict-free)
#pragma unroll
        for (int p = 0; p < 4; p++) {
            int d4 = vd + p * 16;
            float4 vv = *reinterpret_cast<const float4*>(Vb + (size_t)(kg + vk) * HDIM + d4);
            Vt[(d4 + 0) * AP + vk] = f2tf(vv.x);
            Vt[(d4 + 1) * AP + vk] = f2tf(vv.y);
            Vt[(d4 + 2) * AP + vk] = f2tf(vv.z);
            Vt[(d4 + 3) * AP + vk] = f2tf(vv.w);
        }
        __syncthreads();

        // S = Q K^T  (warp: 16 q-rows x 64 kcols)
        float sacc[8][4];
#pragma unroll
        for (int nt = 0; nt < 8; nt++)
#pragma unroll
            for (int j = 0; j < 4; j++) sacc[nt][j] = 0.f;
#pragma unroll
        for (int ks = 0; ks < 64; ks += 8) {
            uint32_t a[4];
            a[0] = Qs[(wm + g) * AP + ks + tig];
            a[1] = Qs[(wm + g + 8) * AP + ks + tig];
            a[2] = Qs[(wm + g) * AP + ks + tig + 4];
            a[3] = Qs[(wm + g + 8) * AP + ks + tig + 4];
#pragma unroll
            for (int nt = 0; nt < 8; nt++) {
                uint32_t b0 = Ks[(nt * 8 + g) * AP + ks + tig];
                uint32_t b1 = Ks[(nt * 8 + g) * AP + ks + tig + 4];
                mma8(sacc[nt], a, b0, b1);
            }
        }
        // scale + causal mask
        const bool need_mask = (kg + 63) > rg0;
#pragma unroll
        for (int nt = 0; nt < 8; nt++) {
#pragma unroll
            for (int j = 0; j < 4; j++) sacc[nt][j] *= 0.125f;
            if (need_mask) {
                int cg = kg + nt * 8 + 2 * tig;
                if (cg     > rg0) sacc[nt][0] = -1e30f;
                if (cg + 1 > rg0) sacc[nt][1] = -1e30f;
                if (cg     > rg1) sacc[nt][2] = -1e30f;
                if (cg + 1 > rg1) sacc[nt][3] = -1e30f;
            }
        }

        // online softmax (row = g / g+8; reduce over tig lanes)
        float rmax0 = -1e30f, rmax1 = -1e30f;
#pragma unroll
        for (int nt = 0; nt < 8; nt++) {
            rmax0 = fmaxf(rmax0, fmaxf(sacc[nt][0], sacc[nt][1]));
            rmax1 = fmaxf(rmax1, fmaxf(sacc[nt][2], sacc[nt][3]));
        }
        rmax0 = fmaxf(rmax0, __shfl_xor_sync(0xffffffffu, rmax0, 1));
        rmax0 = fmaxf(rmax0, __shfl_xor_sync(0xffffffffu, rmax0, 2));
        rmax1 = fmaxf(rmax1, __shfl_xor_sync(0xffffffffu, rmax1, 1));
        rmax1 = fmaxf(rmax1, __shfl_xor_sync(0xffffffffu, rmax1, 2));

        float mn0 = fmaxf(m0, rmax0), mn1 = fmaxf(m1, rmax1);
        float al0 = __expf(m0 - mn0), al1 = __expf(m1 - mn1);
        m0 = mn0; m1 = mn1;

        float rs0 = 0.f, rs1 = 0.f;
#pragma unroll
        for (int nt = 0; nt < 8; nt++) {
            float p0 = __expf(sacc[nt][0] - mn0);
            float p1 = __expf(sacc[nt][1] - mn0);
            float p2 = __expf(sacc[nt][2] - mn1);
            float p3 = __expf(sacc[nt][3] - mn1);
            rs0 += p0 + p1; rs1 += p2 + p3;
            int col = nt * 8 + 2 * tig;
            uint2 u01, u23;
            u01.x = f2tf(p0); u01.y = f2tf(p1);
            u23.x = f2tf(p2); u23.y = f2tf(p3);
            *reinterpret_cast<uint2*>(&Ps[(wm + g) * AP + col])     = u01;
            *reinterpret_cast<uint2*>(&Ps[(wm + g + 8) * AP + col]) = u23;
        }
        rs0 += __shfl_xor_sync(0xffffffffu, rs0, 1);
        rs0 += __shfl_xor_sync(0xffffffffu, rs0, 2);
        rs1 += __shfl_xor_sync(0xffffffffu, rs1, 1);
        rs1 += __shfl_xor_sync(0xffffffffu, rs1, 2);
        l0 = l0 * al0 + rs0;
        l1 = l1 * al1 + rs1;
#pragma unroll
        for (int nt = 0; nt < 8; nt++) {
            oacc[nt][0] *= al0; oacc[nt][1] *= al0;
            oacc[nt][2] *= al1; oacc[nt][3] *= al1;
        }
        __syncwarp();   // Ps rows are warp-private: warp-level sync suffices

        // O += P V   (A = P rows, B = Vt[d][kcol])
#pragma unroll
        for (int ks = 0; ks < 64; ks += 8) {
            uint32_t a[4];
            a[0] = Ps[(wm + g) * AP + ks + tig];
            a[1] = Ps[(wm + g + 8) * AP + ks + tig];
            a[2] = Ps[(wm + g) * AP + ks + tig + 4];
            a[3] = Ps[(wm + g + 8) * AP + ks + tig + 4];
#pragma unroll
            for (int nt = 0; nt < 8; nt++) {
                uint32_t b0 = Vt[(nt * 8 + g) * AP + ks + tig];
                uint32_t b1 = Vt[(nt * 8 + g) * AP + ks + tig + 4];
                mma8(oacc[nt], a, b0, b1);
            }
        }
    }

    const float iv0 = 1.0f / l0, iv1 = 1.0f / l1;
#pragma unroll
    for (int nt = 0; nt < 8; nt++) {
        int col = nt * 8 + 2 * tig;
        float2 v0, v1;
        v0.x = oacc[nt][0] * iv0; v0.y = oacc[nt][1] * iv0;
        v1.x = oacc[nt][2] * iv1; v1.y = oacc[nt][3] * iv1;
        *reinterpret_cast<float2*>(O + ((size_t)bh * SEQ + rg0) * HDIM + col) = v0;
        *reinterpret_cast<float2*>(O + ((size_t)bh * SEQ + rg1) * HDIM + col) = v1;
    }
}

// ---------------- [B,H,S,Hd] -> [B*S, D] gather ----------------
__global__ void gather_heads_kernel(const float* __restrict__ O, float* __restrict__ AO)
{
    int idx = blockIdx.x * blockDim.x + threadIdx.x;
    if (idx >= MROWS * DMODEL / 4) return;
    int e  = idx << 2;
    int m  = e >> 10;
    int dc = e & 1023;
    int h  = dc >> 6;
    int hd = dc & 63;
    int b  = m >> 11;
    int s  = m & 2047;
    float4 val = *reinterpret_cast<const float4*>(
        O + ((size_t)(b * NHEADS + h) * SEQ + s) * HDIM + hd);
    *reinterpret_cast<float4*>(AO + (size_t)e) = val;
}

// ---------------- launcher ----------------
extern "C" void kernel_launch(void* const* d_in, const int* in_sizes, int n_in,
                              void* d_out, int out_size)
{
    const float* x     = (const float*)d_in[0];
    const float* qkv_w = (const float*)d_in[1];
    const float* qkv_b = (const float*)d_in[2];
    const float* out_w = (const float*)d_in[3];
    const float* out_b = (const float*)d_in[4];
    float* out = (float*)d_out;

    float *qkv, *q, *k, *v, *o, *ao;
    cudaGetSymbolAddress((void**)&qkv, g_qkv);
    cudaGetSymbolAddress((void**)&q,   g_q);
    cudaGetSymbolAddress((void**)&k,   g_k);
    cudaGetSymbolAddress((void**)&v,   g_v);
    cudaGetSymbolAddress((void**)&o,   g_o);
    cudaGetSymbolAddress((void**)&ao,  g_ao);

    cudaFuncSetAttribute(attn_tc_kernel,
                         cudaFuncAttributeMaxDynamicSharedMemorySize, ATTN_SMEM);

    // 1) QKV projection: [4096,1024] @ [3072,1024]^T + bias
    dim3 g1(QKVN / 128, MROWS / 128);
    gemm_tf32_nt_bias<<<g1, 256>>>(x, qkv_w, qkv_b, qkv, MROWS, QKVN, DMODEL);

    // 2) RoPE + split into [B,H,S,Hd]
    int nrope = MROWS * NHEADS * (HDIM / 2);
    rope_split_kernel<<<(nrope + 255) / 256, 256>>>(qkv, q, k, v);

    // 3) causal flash attention (tf32 tensor cores)
    dim3 ga(SEQ / 128, BHT);
    attn_tc_kernel<<<ga, 256, ATTN_SMEM>>>(q, k, v, o);

    // 4) gather heads back to [B*S, D]
    int ngather = MROWS * DMODEL / 4;
    gather_heads_kernel<<<(ngather + 255) / 256, 256>>>(o, ao);

    // 5) output projection: [4096,1024] @ [1024,1024]^T + bias
    dim3 g2(DMODEL / 128, MROWS / 128);
    gemm_tf32_nt_bias<<<g2, 256>>>(ao, out_w, out_b, out, MROWS, DMODEL, DMODEL);
}

// round 7
// speedup vs baseline: 1.5672x; 1.5672x over previous
#include <cuda_runtime.h>
#include <math.h>
#include <float.h>
#include <stdint.h>

#define BATCH   2
#define SEQ     2048
#define DMODEL  1024
#define NHEADS  16
#define HDIM    64
#define MROWS   (BATCH*SEQ)     // 4096
#define QKVN    (3*DMODEL)      // 3072
#define BHT     (BATCH*NHEADS)  // 32

// ---------------- scratch (device globals; no allocations allowed) ----------
static __device__ float g_qkv[(size_t)MROWS * QKVN];
static __device__ float g_q  [(size_t)BHT * SEQ * HDIM];
static __device__ float g_k  [(size_t)BHT * SEQ * HDIM];
static __device__ float g_v  [(size_t)BHT * SEQ * HDIM];
static __device__ float g_o  [(size_t)BHT * SEQ * HDIM];
static __device__ float g_ao [(size_t)MROWS * DMODEL];

// ---------------- tf32 helpers ----------------
__device__ __forceinline__ uint32_t f2tf(float f) {
    uint32_t u;
    asm("cvt.rna.tf32.f32 %0, %1;" : "=r"(u) : "f"(f));
    return u;
}

// D = A(16x8) * B(8x8) + D, tf32 in / fp32 out
__device__ __forceinline__ void mma8(float* d, const uint32_t* a, uint32_t b0, uint32_t b1) {
    asm volatile(
        "mma.sync.aligned.m16n8k8.row.col.f32.tf32.tf32.f32 "
        "{%0,%1,%2,%3}, {%4,%5,%6,%7}, {%8,%9}, {%0,%1,%2,%3};"
        : "+f"(d[0]), "+f"(d[1]), "+f"(d[2]), "+f"(d[3])
        : "r"(a[0]), "r"(a[1]), "r"(a[2]), "r"(a[3]), "r"(b0), "r"(b1));
}

// ============ TF32 tensor-core GEMM: C[M,N] = A[M,K] * B[N,K]^T + bias[N] ===
// 128x128 block, k16 chunks, 256 threads = 8 warps (2m x 4n), warp tile 64x32.
// smem tiles stored [row][k] with pad GP=20 -> conflict-free frag LDS + STS.128.
#define GP 20
__global__ __launch_bounds__(256)
void gemm_tf32_nt_bias(const float* __restrict__ A, const float* __restrict__ B,
                       const float* __restrict__ bias, float* __restrict__ C,
                       int M, int N, int K)
{
    __shared__ uint32_t As[128 * GP];
    __shared__ uint32_t Bs[128 * GP];

    const int tid  = threadIdx.x;
    const int warp = tid >> 5, lane = tid & 31;
    const int g    = lane >> 2, tig = lane & 3;
    const int wm   = (warp >> 2) * 64;
    const int wn   = (warp & 3) * 32;
    const int bm   = blockIdx.y * 128;
    const int bn   = blockIdx.x * 128;

    // load mapping: 8 lanes = 8 consecutive rows with same kc (STS.128 phases clean)
    const int kc = ((tid >> 3) & 3) << 2;          // 0,4,8,12
    const int r0 = (tid & 7) + ((tid >> 5) << 3);  // 0..63

    float acc[4][4][4];
#pragma unroll
    for (int mt = 0; mt < 4; mt++)
#pragma unroll
        for (int nt = 0; nt < 4; nt++)
#pragma unroll
            for (int j = 0; j < 4; j++) acc[mt][nt][j] = 0.f;

    float4 ra0, ra1, rb0, rb1;
    ra0 = *reinterpret_cast<const float4*>(A + (size_t)(bm + r0)      * K + kc);
    ra1 = *reinterpret_cast<const float4*>(A + (size_t)(bm + r0 + 64) * K + kc);
    rb0 = *reinterpret_cast<const float4*>(B + (size_t)(bn + r0)      * K + kc);
    rb1 = *reinterpret_cast<const float4*>(B + (size_t)(bn + r0 + 64) * K + kc);
    {
        uint4 u;
        u.x = f2tf(ra0.x); u.y = f2tf(ra0.y); u.z = f2tf(ra0.z); u.w = f2tf(ra0.w);
        *reinterpret_cast<uint4*>(&As[r0 * GP + kc]) = u;
        u.x = f2tf(ra1.x); u.y = f2tf(ra1.y); u.z = f2tf(ra1.z); u.w = f2tf(ra1.w);
        *reinterpret_cast<uint4*>(&As[(r0 + 64) * GP + kc]) = u;
        u.x = f2tf(rb0.x); u.y = f2tf(rb0.y); u.z = f2tf(rb0.z); u.w = f2tf(rb0.w);
        *reinterpret_cast<uint4*>(&Bs[r0 * GP + kc]) = u;
        u.x = f2tf(rb1.x); u.y = f2tf(rb1.y); u.z = f2tf(rb1.z); u.w = f2tf(rb1.w);
        *reinterpret_cast<uint4*>(&Bs[(r0 + 64) * GP + kc]) = u;
    }
    __syncthreads();

    for (int kt = 0; kt < K; kt += 16) {
        const bool nxt = (kt + 16) < K;
        if (nxt) {
            ra0 = *reinterpret_cast<const float4*>(A + (size_t)(bm + r0)      * K + kt + 16 + kc);
            ra1 = *reinterpret_cast<const float4*>(A + (size_t)(bm + r0 + 64) * K + kt + 16 + kc);
            rb0 = *reinterpret_cast<const float4*>(B + (size_t)(bn + r0)      * K + kt + 16 + kc);
            rb1 = *reinterpret_cast<const float4*>(B + (size_t)(bn + r0 + 64) * K + kt + 16 + kc);
        }
#pragma unroll
        for (int ks = 0; ks < 16; ks += 8) {
            uint32_t af[4][4];
#pragma unroll
            for (int mt = 0; mt < 4; mt++) {
                int m0 = wm + mt * 16 + g;
                af[mt][0] = As[m0 * GP + ks + tig];
                af[mt][1] = As[(m0 + 8) * GP + ks + tig];
                af[mt][2] = As[m0 * GP + ks + tig + 4];
                af[mt][3] = As[(m0 + 8) * GP + ks + tig + 4];
            }
#pragma unroll
            for (int nt = 0; nt < 4; nt++) {
                int n0 = wn + nt * 8 + g;
                uint32_t b0 = Bs[n0 * GP + ks + tig];
                uint32_t b1 = Bs[n0 * GP + ks + tig + 4];
#pragma unroll
                for (int mt = 0; mt < 4; mt++)
                    mma8(acc[mt][nt], af[mt], b0, b1);
            }
        }
        if (nxt) {
            __syncthreads();
            uint4 u;
            u.x = f2tf(ra0.x); u.y = f2tf(ra0.y); u.z = f2tf(ra0.z); u.w = f2tf(ra0.w);
            *reinterpret_cast<uint4*>(&As[r0 * GP + kc]) = u;
            u.x = f2tf(ra1.x); u.y = f2tf(ra1.y); u.z = f2tf(ra1.z); u.w = f2tf(ra1.w);
            *reinterpret_cast<uint4*>(&As[(r0 + 64) * GP + kc]) = u;
            u.x = f2tf(rb0.x); u.y = f2tf(rb0.y); u.z = f2tf(rb0.z); u.w = f2tf(rb0.w);
            *reinterpret_cast<uint4*>(&Bs[r0 * GP + kc]) = u;
            u.x = f2tf(rb1.x); u.y = f2tf(rb1.y); u.z = f2tf(rb1.z); u.w = f2tf(rb1.w);
            *reinterpret_cast<uint4*>(&Bs[(r0 + 64) * GP + kc]) = u;
            __syncthreads();
        }
    }

#pragma unroll
    for (int nt = 0; nt < 4; nt++) {
        int cc = bn + wn + nt * 8 + 2 * tig;
        float bv0 = bias[cc], bv1 = bias[cc + 1];
#pragma unroll
        for (int mt = 0; mt < 4; mt++) {
            int rr = bm + wm + mt * 16 + g;
            float2 v0, v1;
            v0.x = acc[mt][nt][0] + bv0; v0.y = acc[mt][nt][1] + bv1;
            v1.x = acc[mt][nt][2] + bv0; v1.y = acc[mt][nt][3] + bv1;
            *reinterpret_cast<float2*>(C + (size_t)rr * N + cc)       = v0;
            *reinterpret_cast<float2*>(C + (size_t)(rr + 8) * N + cc) = v1;
        }
    }
}

// ---------------- RoPE + split qkv[M,3*D] -> q/k/v [B,H,S,Hd] ----------------
__global__ void rope_split_kernel(const float* __restrict__ qkv,
                                  float* __restrict__ q, float* __restrict__ k,
                                  float* __restrict__ v)
{
    int idx = blockIdx.x * blockDim.x + threadIdx.x;
    if (idx >= MROWS * NHEADS * (HDIM / 2)) return;
    int j = idx & 31;
    int h = (idx >> 5) & 15;
    int m = idx >> 9;
    int b = m >> 11;
    int s = m & 2047;

    float inv_freq = 1.0f / powf(10000.0f, (float)j * (1.0f / 32.0f));
    float ang = (float)s * inv_freq;
    float sn, c;
    sincosf(ang, &sn, &c);

    size_t ib = (size_t)m * QKVN + (size_t)h * HDIM;
    size_t ob = ((size_t)(b * NHEADS + h) * SEQ + s) * HDIM;

    float q1 = qkv[ib + j],          q2 = qkv[ib + 32 + j];
    q[ob + j]      = q1 * c  - q2 * sn;
    q[ob + 32 + j] = q1 * sn + q2 * c;

    float k1 = qkv[ib + DMODEL + j], k2 = qkv[ib + DMODEL + 32 + j];
    k[ob + j]      = k1 * c  - k2 * sn;
    k[ob + 32 + j] = k1 * sn + k2 * c;

    v[ob + j]      = qkv[ib + 2 * DMODEL + j];
    v[ob + 32 + j] = qkv[ib + 2 * DMODEL + 32 + j];
}

// ============ TF32 tensor-core causal flash attention ============
// BQ=128, BK=64, 256 threads = 8 warps, warp owns 16 q-rows (no cross-warp
// softmax). smem pad AP=68 -> conflict-free fragment LDS.
#define AP 68
#define ATTN_SMEM ((128 + 64 + 64 + 128) * AP * 4)
__global__ __launch_bounds__(256)
void attn_tc_kernel(const float* __restrict__ Q, const float* __restrict__ K,
                    const float* __restrict__ V, float* __restrict__ O)
{
    extern __shared__ uint32_t sm_u[];
    uint32_t* Qs = sm_u;               // [128][AP]  Q rows (tf32)
    uint32_t* Ks = Qs + 128 * AP;      // [64][AP]   K rows (tf32)
    uint32_t* Vt = Ks + 64 * AP;       // [64][AP]   V transposed: [d][kcol]
    uint32_t* Ps = Vt + 64 * AP;       // [128][AP]  P rows (tf32)

    const int tid  = threadIdx.x;
    const int warp = tid >> 5, lane = tid & 31;
    const int g    = lane >> 2, tig = lane & 3;
    const int wm   = warp * 16;
    const int bh   = blockIdx.y;
    const int qi   = gridDim.x - 1 - blockIdx.x;   // heavy blocks first
    const int q0   = qi * 128;

    const float* Qb = Q + (size_t)bh * SEQ * HDIM;
    const float* Kb = K + (size_t)bh * SEQ * HDIM;
    const float* Vb = V + (size_t)bh * SEQ * HDIM;

    // load Q tile (128x64), row-major, tf32
#pragma unroll
    for (int p = 0; p < 8; p++) {
        int idx = tid + p * 256;
        int row = idx >> 4, c4 = (idx & 15) << 2;
        float4 val = *reinterpret_cast<const float4*>(Qb + (size_t)(q0 + row) * HDIM + c4);
        uint4 u;
        u.x = f2tf(val.x); u.y = f2tf(val.y); u.z = f2tf(val.z); u.w = f2tf(val.w);
        *reinterpret_cast<uint4*>(&Qs[row * AP + c4]) = u;
    }

    float oacc[8][4];
#pragma unroll
    for (int nt = 0; nt < 8; nt++)
#pragma unroll
        for (int j = 0; j < 4; j++) oacc[nt][j] = 0.f;
    float m0 = -1e30f, m1 = -1e30f, l0 = 0.f, l1 = 0.f;

    const int vk = tid & 63;           // kcol owned for V transpose store
    const int vd = (tid >> 6) << 2;    // d4 base

    const int rg0 = q0 + wm + g;
    const int rg1 = rg0 + 8;

    const int nkt = (q0 >> 6) + 2;
    for (int kt = 0; kt < nkt; kt++) {
        const int kg = kt << 6;
        __syncthreads();   // previous iteration's consumers of Ks/Vt done
        // K tile [64][64] row-major
#pragma unroll
        for (int p = 0; p < 4; p++) {
            int idx = tid + p * 256;
            int row = idx >> 4, c4 = (idx & 15) << 2;
            float4 kv = *reinterpret_cast<const float4*>(Kb + (size_t)(kg + row) * HDIM + c4);
            uint4 u;
            u.x = f2tf(kv.x); u.y = f2tf(kv.y); u.z = f2tf(kv.z); u.w = f2tf(kv.w);
            *reinterpret_cast<uint4*>(&Ks[row * AP + c4]) = u;
        }
        // V tile transposed to [d][kcol] (lanes = consecutive kcols -> STS conflict-free)
#pragma unroll
        for (int p = 0; p < 4; p++) {
            int d4 = vd + p * 16;
            float4 vv = *reinterpret_cast<const float4*>(Vb + (size_t)(kg + vk) * HDIM + d4);
            Vt[(d4 + 0) * AP + vk] = f2tf(vv.x);
            Vt[(d4 + 1) * AP + vk] = f2tf(vv.y);
            Vt[(d4 + 2) * AP + vk] = f2tf(vv.z);
            Vt[(d4 + 3) * AP + vk] = f2tf(vv.w);
        }
        __syncthreads();

        // S = Q K^T  (warp: 16 q-rows x 64 kcols)
        float sacc[8][4];
#pragma unroll
        for (int nt = 0; nt < 8; nt++)
#pragma unroll
            for (int j = 0; j < 4; j++) sacc[nt][j] = 0.f;
#pragma unroll
        for (int ks = 0; ks < 64; ks += 8) {
            uint32_t a[4];
            a[0] = Qs[(wm + g) * AP + ks + tig];
            a[1] = Qs[(wm + g + 8) * AP + ks + tig];
            a[2] = Qs[(wm + g) * AP + ks + tig + 4];
            a[3] = Qs[(wm + g + 8) * AP + ks + tig + 4];
#pragma unroll
            for (int nt = 0; nt < 8; nt++) {
                uint32_t b0 = Ks[(nt * 8 + g) * AP + ks + tig];
                uint32_t b1 = Ks[(nt * 8 + g) * AP + ks + tig + 4];
                mma8(sacc[nt], a, b0, b1);
            }
        }
        // scale + causal mask
        const bool need_mask = (kg + 63) > rg0;
#pragma unroll
        for (int nt = 0; nt < 8; nt++) {
#pragma unroll
            for (int j = 0; j < 4; j++) sacc[nt][j] *= 0.125f;
            if (need_mask) {
                int cg = kg + nt * 8 + 2 * tig;
                if (cg     > rg0) sacc[nt][0] = -1e30f;
                if (cg + 1 > rg0) sacc[nt][1] = -1e30f;
                if (cg     > rg1) sacc[nt][2] = -1e30f;
                if (cg + 1 > rg1) sacc[nt][3] = -1e30f;
            }
        }

        // online softmax (row = g / g+8; reduce over tig lanes)
        float rmax0 = -1e30f, rmax1 = -1e30f;
#pragma unroll
        for (int nt = 0; nt < 8; nt++) {
            rmax0 = fmaxf(rmax0, fmaxf(sacc[nt][0], sacc[nt][1]));
            rmax1 = fmaxf(rmax1, fmaxf(sacc[nt][2], sacc[nt][3]));
        }
        rmax0 = fmaxf(rmax0, __shfl_xor_sync(0xffffffffu, rmax0, 1));
        rmax0 = fmaxf(rmax0, __shfl_xor_sync(0xffffffffu, rmax0, 2));
        rmax1 = fmaxf(rmax1, __shfl_xor_sync(0xffffffffu, rmax1, 1));
        rmax1 = fmaxf(rmax1, __shfl_xor_sync(0xffffffffu, rmax1, 2));

        float mn0 = fmaxf(m0, rmax0), mn1 = fmaxf(m1, rmax1);
        float al0 = __expf(m0 - mn0), al1 = __expf(m1 - mn1);
        m0 = mn0; m1 = mn1;

        float rs0 = 0.f, rs1 = 0.f;
#pragma unroll
        for (int nt = 0; nt < 8; nt++) {
            float p0 = __expf(sacc[nt][0] - mn0);
            float p1 = __expf(sacc[nt][1] - mn0);
            float p2 = __expf(sacc[nt][2] - mn1);
            float p3 = __expf(sacc[nt][3] - mn1);
            rs0 += p0 + p1; rs1 += p2 + p3;
            int col = nt * 8 + 2 * tig;
            uint2 u01, u23;
            u01.x = f2tf(p0); u01.y = f2tf(p1);
            u23.x = f2tf(p2); u23.y = f2tf(p3);
            *reinterpret_cast<uint2*>(&Ps[(wm + g) * AP + col])     = u01;
            *reinterpret_cast<uint2*>(&Ps[(wm + g + 8) * AP + col]) = u23;
        }
        rs0 += __shfl_xor_sync(0xffffffffu, rs0, 1);
        rs0 += __shfl_xor_sync(0xffffffffu, rs0, 2);
        rs1 += __shfl_xor_sync(0xffffffffu, rs1, 1);
        rs1 += __shfl_xor_sync(0xffffffffu, rs1, 2);
        l0 = l0 * al0 + rs0;
        l1 = l1 * al1 + rs1;
#pragma unroll
        for (int nt = 0; nt < 8; nt++) {
            oacc[nt][0] *= al0; oacc[nt][1] *= al0;
            oacc[nt][2] *= al1; oacc[nt][3] *= al1;
        }
        __syncwarp();   // Ps rows are warp-private: warp-level sync suffices

        // O += P V   (A = P rows, B = Vt[d][kcol])
#pragma unroll
        for (int ks = 0; ks < 64; ks += 8) {
            uint32_t a[4];
            a[0] = Ps[(wm + g) * AP + ks + tig];
            a[1] = Ps[(wm + g + 8) * AP + ks + tig];
            a[2] = Ps[(wm + g) * AP + ks + tig + 4];
            a[3] = Ps[(wm + g + 8) * AP + ks + tig + 4];
#pragma unroll
            for (int nt = 0; nt < 8; nt++) {
                uint32_t b0 = Vt[(nt * 8 + g) * AP + ks + tig];
                uint32_t b1 = Vt[(nt * 8 + g) * AP + ks + tig + 4];
                mma8(oacc[nt], a, b0, b1);
            }
        }
    }

    const float iv0 = 1.0f / l0, iv1 = 1.0f / l1;
#pragma unroll
    for (int nt = 0; nt < 8; nt++) {
        int col = nt * 8 + 2 * tig;
        float2 v0, v1;
        v0.x = oacc[nt][0] * iv0; v0.y = oacc[nt][1] * iv0;
        v1.x = oacc[nt][2] * iv1; v1.y = oacc[nt][3] * iv1;
        *reinterpret_cast<float2*>(O + ((size_t)bh * SEQ + rg0) * HDIM + col) = v0;
        *reinterpret_cast<float2*>(O + ((size_t)bh * SEQ + rg1) * HDIM + col) = v1;
    }
}

// ---------------- [B,H,S,Hd] -> [B*S, D] gather ----------------
__global__ void gather_heads_kernel(const float* __restrict__ O, float* __restrict__ AO)
{
    int idx = blockIdx.x * blockDim.x + threadIdx.x;
    if (idx >= MROWS * DMODEL / 4) return;
    int e  = idx << 2;
    int m  = e >> 10;
    int dc = e & 1023;
    int h  = dc >> 6;
    int hd = dc & 63;
    int b  = m >> 11;
    int s  = m & 2047;
    float4 val = *reinterpret_cast<const float4*>(
        O + ((size_t)(b * NHEADS + h) * SEQ + s) * HDIM + hd);
    *reinterpret_cast<float4*>(AO + (size_t)e) = val;
}

// ---------------- launcher ----------------
extern "C" void kernel_launch(void* const* d_in, const int* in_sizes, int n_in,
                              void* d_out, int out_size)
{
    const float* x     = (const float*)d_in[0];
    const float* qkv_w = (const float*)d_in[1];
    const float* qkv_b = (const float*)d_in[2];
    const float* out_w = (const float*)d_in[3];
    const float* out_b = (const float*)d_in[4];
    float* out = (float*)d_out;

    float *qkv, *q, *k, *v, *o, *ao;
    cudaGetSymbolAddress((void**)&qkv, g_qkv);
    cudaGetSymbolAddress((void**)&q,   g_q);
    cudaGetSymbolAddress((void**)&k,   g_k);
    cudaGetSymbolAddress((void**)&v,   g_v);
    cudaGetSymbolAddress((void**)&o,   g_o);
    cudaGetSymbolAddress((void**)&ao,  g_ao);

    cudaFuncSetAttribute(attn_tc_kernel,
                         cudaFuncAttributeMaxDynamicSharedMemorySize, ATTN_SMEM);

    // 1) QKV projection: [4096,1024] @ [3072,1024]^T + bias
    dim3 g1(QKVN / 128, MROWS / 128);
    gemm_tf32_nt_bias<<<g1, 256>>>(x, qkv_w, qkv_b, qkv, MROWS, QKVN, DMODEL);

    // 2) RoPE + split into [B,H,S,Hd]
    int nrope = MROWS * NHEADS * (HDIM / 2);
    rope_split_kernel<<<(nrope + 255) / 256, 256>>>(qkv, q, k, v);

    // 3) causal flash attention (tf32 tensor cores)
    dim3 ga(SEQ / 128, BHT);
    attn_tc_kernel<<<ga, 256, ATTN_SMEM>>>(q, k, v, o);

    // 4) gather heads back to [B*S, D]
    int ngather = MROWS * DMODEL / 4;
    gather_heads_kernel<<<(ngather + 255) / 256, 256>>>(o, ao);

    // 5) output projection: [4096,1024] @ [1024,1024]^T + bias
    dim3 g2(DMODEL / 128, MROWS / 128);
    gemm_tf32_nt_bias<<<g2, 256>>>(ao, out_w, out_b, out, MROWS, DMODEL, DMODEL);
}